// round 8
// baseline (speedup 1.0000x reference)
#include <cuda_runtime.h>
#include <cuda_bf16.h>

#define THREADS 256
#define T_STEPS 20
#define BETA 0.9f
#define THR 1.0f

typedef unsigned int u32;

// ---- smem byte offsets (all regions disjoint — groups are unsynchronized) ----
#define SW1 0            // 3 x 128 x 32B
#define SW2 12288        // 3 x 128 x 256B
#define SW3 110592       // 3 x 64 x 256B
#define SW4 159744       // 3 x 16 x 128B
#define SS1 165888       // 64 x 256B
#define SS2 182272       // 64 x 256B
#define SS3 198656       // 64 x 128B
#define SXS 206848       // 3 x 64 x 32B
#define SM_TOTAL 212992

__device__ __forceinline__ float bfv(float v) { return __bfloat162float(__float2bfloat16(v)); }

__device__ __forceinline__ void ldsm4(u32 a[4], u32 addr) {
    asm volatile("ldmatrix.sync.aligned.m8n8.x4.shared.b16 {%0,%1,%2,%3}, [%4];"
        : "=r"(a[0]), "=r"(a[1]), "=r"(a[2]), "=r"(a[3]) : "r"(addr));
}
__device__ __forceinline__ void mma_bf16(float d[4], const u32 a[4], u32 b0, u32 b1) {
    asm volatile("mma.sync.aligned.m16n8k16.row.col.f32.bf16.bf16.f32 "
        "{%0,%1,%2,%3}, {%4,%5,%6,%7}, {%8,%9}, {%0,%1,%2,%3};"
        : "+f"(d[0]), "+f"(d[1]), "+f"(d[2]), "+f"(d[3])
        : "r"(a[0]), "r"(a[1]), "r"(a[2]), "r"(a[3]), "r"(b0), "r"(b1));
}
__device__ __forceinline__ void sts32(u32 addr, u32 v) {
    asm volatile("st.shared.b32 [%0], %1;" :: "r"(addr), "r"(v) : "memory");
}

__device__ __forceinline__ void lif4(float* mem, const float* d, u32 &p0, u32 &p1) {
    float s[4];
#pragma unroll
    for (int e = 0; e < 4; e++) {
        float m = mem[e];
        float reset = (m > THR) ? 1.0f : 0.0f;
        m = fmaf(BETA, m, d[e]) - reset;
        mem[e] = m;
        s[e] = (m > THR) ? 1.0f : 0.0f;
    }
    p0 = (s[0] != 0.0f ? 0x3F80u : 0u) | (s[1] != 0.0f ? 0x3F800000u : 0u);
    p1 = (s[2] != 0.0f ? 0x3F80u : 0u) | (s[3] != 0.0f ? 0x3F800000u : 0u);
}

__global__ void __launch_bounds__(THREADS, 1)
snn_mma_kernel(const float* __restrict__ x,
               const float* __restrict__ w1g,
               const float* __restrict__ w2g,
               const float* __restrict__ w3g,
               const float* __restrict__ w4g,
               float* __restrict__ out,
               int Btot)
{
    extern __shared__ char sm[];
    u32 smb;
    asm("{ .reg .u64 t; cvta.to.shared.u64 t, %1; cvt.u32.u64 %0, t; }"
        : "=r"(smb) : "l"(sm));

    const int tid  = threadIdx.x;
    const int w    = tid >> 5;
    const int lane = tid & 31;
    const int g    = w >> 2;        // group 0/1 (batches 32g..32g+31)
    const int wg   = w & 3;         // warp-in-group
    const int tg   = tid & 127;     // thread-in-group
    const int bm   = 32 * g;
    const int b0   = blockIdx.x * 64;

    // ---- stage weights: 3-way exact bf16 split + XOR swizzle ----
    for (int idx = tid; idx < 128 * 128; idx += THREADS) {
        int n = idx >> 7, k = idx & 127;
        float v = w2g[idx];
        float r1_ = v - bfv(v);
        float r2_ = r1_ - bfv(r1_);
        u32 off = (u32)(n * 256 + (((k >> 3) ^ (n & 7)) << 4) + (k & 7) * 2);
        *(__nv_bfloat16*)(sm + SW2 +     0 + off) = __float2bfloat16(v);
        *(__nv_bfloat16*)(sm + SW2 + 32768 + off) = __float2bfloat16(r1_);
        *(__nv_bfloat16*)(sm + SW2 + 65536 + off) = __float2bfloat16(r2_);
    }
    for (int idx = tid; idx < 64 * 128; idx += THREADS) {
        int n = idx >> 7, k = idx & 127;
        float v = w3g[idx];
        float r1_ = v - bfv(v);
        float r2_ = r1_ - bfv(r1_);
        u32 off = (u32)(n * 256 + (((k >> 3) ^ (n & 7)) << 4) + (k & 7) * 2);
        *(__nv_bfloat16*)(sm + SW3 +     0 + off) = __float2bfloat16(v);
        *(__nv_bfloat16*)(sm + SW3 + 16384 + off) = __float2bfloat16(r1_);
        *(__nv_bfloat16*)(sm + SW3 + 32768 + off) = __float2bfloat16(r2_);
    }
    for (int idx = tid; idx < 128 * 16; idx += THREADS) {
        int n = idx >> 4, k = idx & 15;
        float v = w1g[idx];
        float r1_ = v - bfv(v);
        float r2_ = r1_ - bfv(r1_);
        u32 off = (u32)(n * 32 + (((k >> 3) ^ (n & 1)) << 4) + (k & 7) * 2);
        *(__nv_bfloat16*)(sm + SW1 +    0 + off) = __float2bfloat16(v);
        *(__nv_bfloat16*)(sm + SW1 + 4096 + off) = __float2bfloat16(r1_);
        *(__nv_bfloat16*)(sm + SW1 + 8192 + off) = __float2bfloat16(r2_);
    }
    for (int idx = tid; idx < 16 * 64; idx += THREADS) {
        int n = idx >> 6, k = idx & 63;
        float v = (n < 10) ? w4g[n * 64 + k] : 0.0f;
        float r1_ = v - bfv(v);
        float r2_ = r1_ - bfv(r1_);
        u32 off = (u32)(n * 128 + (((k >> 3) ^ (n & 7)) << 4) + (k & 7) * 2);
        *(__nv_bfloat16*)(sm + SW4 +    0 + off) = __float2bfloat16(v);
        *(__nv_bfloat16*)(sm + SW4 + 2048 + off) = __float2bfloat16(r1_);
        *(__nv_bfloat16*)(sm + SW4 + 4096 + off) = __float2bfloat16(r2_);
    }

    // ---- lane roles ----
    const int arow = ((lane >> 3) & 1) * 8 + (lane & 7);
    const int ac   = lane >> 4;
    const int brow = ((lane >> 4) << 3) + (lane & 7);
    const int badd = (lane >> 3) & 1;
    const int r_   = lane >> 2;
    const int c_   = lane & 3;
    const u32 rx8  = (u32)(lane & 7) << 4;

    // ---- membranes ----
    float m1[32], m2[32], m3[16], m4[8];
#pragma unroll
    for (int i = 0; i < 32; i++) { m1[i] = 0.f; m2[i] = 0.f; }
#pragma unroll
    for (int i = 0; i < 16; i++) m3[i] = 0.f;
#pragma unroll
    for (int i = 0; i < 8; i++)  m4[i] = 0.f;

    __syncthreads();

    // ---- hoist L1 B fragments (constant over t): warp N=32 at nbase=32*wg ----
    u32 bw1[3][2][4];
#pragma unroll
    for (int lv = 0; lv < 3; lv++)
#pragma unroll
        for (int bb = 0; bb < 2; bb++)
            ldsm4(bw1[lv][bb], smb + SW1 + (u32)(lv * 4096 + (32 * wg + 16 * bb + brow) * 32)
                               + (((u32)badd << 4) ^ ((u32)(brow & 1) << 4)));

#define BARG() asm volatile("bar.sync %0, 128;" :: "r"(g + 1) : "memory")

    for (int t = 0; t < T_STEPS; t++) {
        // ===== group stages its own x splits (32 b x 16 f, 3 levels) =====
        {
            int bl = tg >> 2, f4 = (tg & 3) << 2;
            int br = bm + bl;
            float4 v = *(const float4*)(x + ((size_t)t * (size_t)Btot + (size_t)(b0 + br)) * 16 + f4);
            float h0 = bfv(v.x), h1 = bfv(v.y), h2 = bfv(v.z), h3 = bfv(v.w);
            float e0 = v.x - h0, e1 = v.y - h1, e2 = v.z - h2, e3 = v.w - h3;
            float g0 = bfv(e0), g1 = bfv(e1), g2 = bfv(e2), g3 = bfv(e3);
            float f0 = e0 - g0, f1 = e1 - g1, f2 = e2 - g2, f3 = e3 - g3;
            u32 base = smb + SXS + (u32)(br * 32 + (((f4 >> 3) ^ (bl & 1)) << 4) + (f4 & 7) * 2);
            u32 p;
            p = ((u32)__bfloat16_as_ushort(__float2bfloat16(v.x))) | ((u32)__bfloat16_as_ushort(__float2bfloat16(v.y)) << 16);
            sts32(base, p);
            p = ((u32)__bfloat16_as_ushort(__float2bfloat16(v.z))) | ((u32)__bfloat16_as_ushort(__float2bfloat16(v.w)) << 16);
            sts32(base + 4, p);
            p = ((u32)__bfloat16_as_ushort(__float2bfloat16(e0))) | ((u32)__bfloat16_as_ushort(__float2bfloat16(e1)) << 16);
            sts32(base + 2048, p);
            p = ((u32)__bfloat16_as_ushort(__float2bfloat16(e2))) | ((u32)__bfloat16_as_ushort(__float2bfloat16(e3)) << 16);
            sts32(base + 2048 + 4, p);
            p = ((u32)__bfloat16_as_ushort(__float2bfloat16(f0))) | ((u32)__bfloat16_as_ushort(__float2bfloat16(f1)) << 16);
            sts32(base + 4096, p);
            p = ((u32)__bfloat16_as_ushort(__float2bfloat16(f2))) | ((u32)__bfloat16_as_ushort(__float2bfloat16(f3)) << 16);
            sts32(base + 4096 + 4, p);
        }
        BARG();

        // ===== L1: group 32x128, warp M=32 x N=32, K=16, 6 split terms =====
        {
            float acc[32];
#pragma unroll
            for (int i = 0; i < 32; i++) acc[i] = 0.f;
            const int la[6] = {0, 0, 1, 0, 1, 2};
            const int lb[6] = {0, 1, 0, 2, 1, 0};
#pragma unroll
            for (int M = 0; M < 2; M++) {
                u32 ax[3][4];
#pragma unroll
                for (int lv = 0; lv < 3; lv++)
                    ldsm4(ax[lv], smb + SXS + (u32)(lv * 2048 + (bm + 16 * M + arow) * 32)
                                  + (((u32)ac << 4) ^ ((u32)(arow & 1) << 4)));
#pragma unroll
                for (int s = 0; s < 6; s++)
#pragma unroll
                    for (int bb = 0; bb < 2; bb++) {
                        mma_bf16(&acc[(M * 4 + 2 * bb + 0) * 4], ax[la[s]], bw1[lb[s]][bb][0], bw1[lb[s]][bb][1]);
                        mma_bf16(&acc[(M * 4 + 2 * bb + 1) * 4], ax[la[s]], bw1[lb[s]][bb][2], bw1[lb[s]][bb][3]);
                    }
            }
#pragma unroll
            for (int M = 0; M < 2; M++)
#pragma unroll
                for (int j = 0; j < 4; j++) {
                    u32 p0, p1;
                    lif4(&m1[(M * 4 + j) * 4], &acc[(M * 4 + j) * 4], p0, p1);
                    u32 a0 = smb + SS1 + (u32)((bm + 16 * M + r_) * 256)
                             + (((u32)(4 * wg + j) << 4) ^ ((u32)r_ << 4)) + 4 * c_;
                    sts32(a0, p0);
                    sts32(a0 + 8 * 256, p1);
                }
        }
        BARG();

        // ===== L2: group 32x128, warp M=32 x N=32, K=128, 3 splits =====
        {
            float acc[32];
#pragma unroll
            for (int i = 0; i < 32; i++) acc[i] = 0.f;
#pragma unroll
            for (int kc = 0; kc < 8; kc++) {
                u32 a_[2][4];
#pragma unroll
                for (int M = 0; M < 2; M++)
                    ldsm4(a_[M], smb + SS1 + (u32)((bm + 16 * M + arow) * 256)
                                 + (((u32)(2 * kc + ac) << 4) ^ rx8));
#pragma unroll
                for (int s = 0; s < 3; s++) {
                    u32 b_[2][4];
#pragma unroll
                    for (int bb = 0; bb < 2; bb++)
                        ldsm4(b_[bb], smb + SW2 + (u32)(s * 32768 + (32 * wg + 16 * bb + brow) * 256)
                                      + (((u32)(2 * kc + badd) << 4) ^ rx8));
#pragma unroll
                    for (int M = 0; M < 2; M++)
#pragma unroll
                        for (int bb = 0; bb < 2; bb++) {
                            mma_bf16(&acc[(M * 4 + 2 * bb + 0) * 4], a_[M], b_[bb][0], b_[bb][1]);
                            mma_bf16(&acc[(M * 4 + 2 * bb + 1) * 4], a_[M], b_[bb][2], b_[bb][3]);
                        }
                }
            }
#pragma unroll
            for (int M = 0; M < 2; M++)
#pragma unroll
                for (int j = 0; j < 4; j++) {
                    u32 p0, p1;
                    lif4(&m2[(M * 4 + j) * 4], &acc[(M * 4 + j) * 4], p0, p1);
                    u32 a0 = smb + SS2 + (u32)((bm + 16 * M + r_) * 256)
                             + (((u32)(4 * wg + j) << 4) ^ ((u32)r_ << 4)) + 4 * c_;
                    sts32(a0, p0);
                    sts32(a0 + 8 * 256, p1);
                }
        }
        BARG();

        // ===== L3: group 32x64, warp M=32 x N=16 (n16-block = wg), K=128 =====
        {
            float acc[16];
#pragma unroll
            for (int i = 0; i < 16; i++) acc[i] = 0.f;
#pragma unroll
            for (int kc = 0; kc < 8; kc++) {
                u32 a_[2][4];
#pragma unroll
                for (int M = 0; M < 2; M++)
                    ldsm4(a_[M], smb + SS2 + (u32)((bm + 16 * M + arow) * 256)
                                 + (((u32)(2 * kc + ac) << 4) ^ rx8));
#pragma unroll
                for (int s = 0; s < 3; s++) {
                    u32 b_[4];
                    ldsm4(b_, smb + SW3 + (u32)(s * 16384 + (16 * wg + brow) * 256)
                              + (((u32)(2 * kc + badd) << 4) ^ rx8));
#pragma unroll
                    for (int M = 0; M < 2; M++) {
                        mma_bf16(&acc[(M * 2 + 0) * 4], a_[M], b_[0], b_[1]);
                        mma_bf16(&acc[(M * 2 + 1) * 4], a_[M], b_[2], b_[3]);
                    }
                }
            }
#pragma unroll
            for (int M = 0; M < 2; M++)
#pragma unroll
                for (int nb = 0; nb < 2; nb++) {
                    u32 p0, p1;
                    lif4(&m3[(M * 2 + nb) * 4], &acc[(M * 2 + nb) * 4], p0, p1);
                    u32 a0 = smb + SS3 + (u32)((bm + 16 * M + r_) * 128)
                             + (((u32)(2 * wg + nb) << 4) ^ ((u32)r_ << 4)) + 4 * c_;
                    sts32(a0, p0);
                    sts32(a0 + 8 * 128, p1);
                }
        }
        BARG();

        // ===== L4: group 32x10, warps wg<2: M-block=wg, N=16 (10 real), K=64 =====
        if (wg < 2) {
            float acc[8];
#pragma unroll
            for (int i = 0; i < 8; i++) acc[i] = 0.f;
#pragma unroll
            for (int kc = 0; kc < 4; kc++) {
                u32 a_[4];
                ldsm4(a_, smb + SS3 + (u32)((bm + 16 * wg + arow) * 128)
                          + (((u32)(2 * kc + ac) << 4) ^ rx8));
#pragma unroll
                for (int s = 0; s < 3; s++) {
                    u32 b_[4];
                    ldsm4(b_, smb + SW4 + (u32)(s * 2048 + brow * 128)
                              + (((u32)(2 * kc + badd) << 4) ^ rx8));
                    mma_bf16(&acc[0], a_, b_[0], b_[1]);
                    mma_bf16(&acc[4], a_, b_[2], b_[3]);
                }
            }
            u32 q0, q1, q2, q3;
            lif4(&m4[0], &acc[0], q0, q1);
            lif4(&m4[4], &acc[4], q2, q3);
            float s4[8];
#pragma unroll
            for (int e = 0; e < 8; e++) {
                // recompute spike floats from membranes (already updated)
                s4[e] = (m4[e] > THR) ? 1.0f : 0.0f;
            }
            size_t row0 = (size_t)t * (size_t)Btot + (size_t)(b0 + bm + 16 * wg + r_);
            *(float2*)(out + row0 * 10 + 2 * c_)       = make_float2(s4[0], s4[1]);
            *(float2*)(out + (row0 + 8) * 10 + 2 * c_) = make_float2(s4[2], s4[3]);
            if (c_ == 0) {
                *(float2*)(out + row0 * 10 + 8)       = make_float2(s4[4], s4[5]);
                *(float2*)(out + (row0 + 8) * 10 + 8) = make_float2(s4[6], s4[7]);
            }
        }
        // no barrier needed after L4 (next phase writes SXS, untouched here)
    }
#undef BARG
}

extern "C" void kernel_launch(void* const* d_in, const int* in_sizes, int n_in,
                              void* d_out, int out_size) {
    const float* x  = (const float*)d_in[0];
    const float* w1 = (const float*)d_in[1];
    const float* w2 = (const float*)d_in[2];
    const float* w3 = (const float*)d_in[3];
    const float* w4 = (const float*)d_in[4];
    float* out = (float*)d_out;

    const int Btot = in_sizes[0] / (T_STEPS * 16);  // 65536
    const int grid = Btot / 64;                     // 1024

    cudaFuncSetAttribute(snn_mma_kernel,
                         cudaFuncAttributeMaxDynamicSharedMemorySize,
                         SM_TOTAL);
    snn_mma_kernel<<<grid, THREADS, SM_TOTAL>>>(x, w1, w2, w3, w4, out, Btot);
}

// round 9
// speedup vs baseline: 1.3747x; 1.3747x over previous
#include <cuda_runtime.h>
#include <cuda_bf16.h>

#define THREADS 512
#define T_STEPS 20
#define BETA 0.9f
#define THR 1.0f

typedef unsigned int u32;

// ---- smem byte offsets (aliasing identical to R7) ----
#define SW1 0            // 3 x 128 x 32B
#define SW2 12288        // 3 x 128 x 256B
#define SW3 110592       // 3 x 64 x 256B
#define SW4 159744       // 3 x 16 x 128B
#define SS1 165888       // 64 x 256B (s1; s3 aliases)
#define SS2 182272       // 64 x 256B (s2; x-splits alias)
#define SS3 SS1
#define SXS SS2
#define SM_TOTAL 198656

__device__ __forceinline__ float bfv(float v) { return __bfloat162float(__float2bfloat16(v)); }
__device__ __forceinline__ u32 bfb(float v) { return (u32)__bfloat16_as_ushort(__float2bfloat16(v)); }

__device__ __forceinline__ void ldsm4(u32 a[4], u32 addr) {
    asm volatile("ldmatrix.sync.aligned.m8n8.x4.shared.b16 {%0,%1,%2,%3}, [%4];"
        : "=r"(a[0]), "=r"(a[1]), "=r"(a[2]), "=r"(a[3]) : "r"(addr));
}
__device__ __forceinline__ void mma_bf16(float d[4], const u32 a[4], u32 b0, u32 b1) {
    asm volatile("mma.sync.aligned.m16n8k16.row.col.f32.bf16.bf16.f32 "
        "{%0,%1,%2,%3}, {%4,%5,%6,%7}, {%8,%9}, {%0,%1,%2,%3};"
        : "+f"(d[0]), "+f"(d[1]), "+f"(d[2]), "+f"(d[3])
        : "r"(a[0]), "r"(a[1]), "r"(a[2]), "r"(a[3]), "r"(b0), "r"(b1));
}
__device__ __forceinline__ void sts32(u32 addr, u32 v) {
    asm volatile("st.shared.b32 [%0], %1;" :: "r"(addr), "r"(v) : "memory");
}

__device__ __forceinline__ void lif4(float* mem, const float* d, u32 &p0, u32 &p1) {
    float s[4];
#pragma unroll
    for (int e = 0; e < 4; e++) {
        float m = mem[e];
        float reset = (m > THR) ? 1.0f : 0.0f;
        m = fmaf(BETA, m, d[e]) - reset;
        mem[e] = m;
        s[e] = (m > THR) ? 1.0f : 0.0f;
    }
    p0 = (s[0] != 0.0f ? 0x3F80u : 0u) | (s[1] != 0.0f ? 0x3F800000u : 0u);
    p1 = (s[2] != 0.0f ? 0x3F80u : 0u) | (s[3] != 0.0f ? 0x3F800000u : 0u);
}

__global__ void __launch_bounds__(THREADS, 1)
snn_mma_kernel(const float* __restrict__ x,
               const float* __restrict__ w1g,
               const float* __restrict__ w2g,
               const float* __restrict__ w3g,
               const float* __restrict__ w4g,
               float* __restrict__ out,
               int Btot)
{
    extern __shared__ char sm[];
    u32 smb;
    asm("{ .reg .u64 t; cvta.to.shared.u64 t, %1; cvt.u32.u64 %0, t; }"
        : "=r"(smb) : "l"(sm));

    const int tid  = threadIdx.x;
    const int w    = tid >> 5;
    const int lane = tid & 31;
    const int b0   = blockIdx.x * 64;

    // ---- stage weights: 3-way exact bf16 split + XOR swizzle (as R7) ----
    for (int idx = tid; idx < 128 * 128; idx += THREADS) {
        int n = idx >> 7, k = idx & 127;
        float v = w2g[idx];
        float r1_ = v - bfv(v);
        float r2_ = r1_ - bfv(r1_);
        u32 off = (u32)(n * 256 + (((k >> 3) ^ (n & 7)) << 4) + (k & 7) * 2);
        *(__nv_bfloat16*)(sm + SW2 +     0 + off) = __float2bfloat16(v);
        *(__nv_bfloat16*)(sm + SW2 + 32768 + off) = __float2bfloat16(r1_);
        *(__nv_bfloat16*)(sm + SW2 + 65536 + off) = __float2bfloat16(r2_);
    }
    for (int idx = tid; idx < 64 * 128; idx += THREADS) {
        int n = idx >> 7, k = idx & 127;
        float v = w3g[idx];
        float r1_ = v - bfv(v);
        float r2_ = r1_ - bfv(r1_);
        u32 off = (u32)(n * 256 + (((k >> 3) ^ (n & 7)) << 4) + (k & 7) * 2);
        *(__nv_bfloat16*)(sm + SW3 +     0 + off) = __float2bfloat16(v);
        *(__nv_bfloat16*)(sm + SW3 + 16384 + off) = __float2bfloat16(r1_);
        *(__nv_bfloat16*)(sm + SW3 + 32768 + off) = __float2bfloat16(r2_);
    }
    for (int idx = tid; idx < 128 * 16; idx += THREADS) {
        int n = idx >> 4, k = idx & 15;
        float v = w1g[idx];
        float r1_ = v - bfv(v);
        float r2_ = r1_ - bfv(r1_);
        u32 off = (u32)(n * 32 + (((k >> 3) ^ (n & 1)) << 4) + (k & 7) * 2);
        *(__nv_bfloat16*)(sm + SW1 +    0 + off) = __float2bfloat16(v);
        *(__nv_bfloat16*)(sm + SW1 + 4096 + off) = __float2bfloat16(r1_);
        *(__nv_bfloat16*)(sm + SW1 + 8192 + off) = __float2bfloat16(r2_);
    }
    for (int idx = tid; idx < 16 * 64; idx += THREADS) {
        int n = idx >> 6, k = idx & 63;
        float v = (n < 10) ? w4g[n * 64 + k] : 0.0f;
        float r1_ = v - bfv(v);
        float r2_ = r1_ - bfv(r1_);
        u32 off = (u32)(n * 128 + (((k >> 3) ^ (n & 7)) << 4) + (k & 7) * 2);
        *(__nv_bfloat16*)(sm + SW4 +    0 + off) = __float2bfloat16(v);
        *(__nv_bfloat16*)(sm + SW4 + 2048 + off) = __float2bfloat16(r1_);
        *(__nv_bfloat16*)(sm + SW4 + 4096 + off) = __float2bfloat16(r2_);
    }

    // ---- lane roles ----
    const int arow = ((lane >> 3) & 1) * 8 + (lane & 7);
    const int ac   = lane >> 4;
    const int brow = ((lane >> 4) << 3) + (lane & 7);
    const int badd = (lane >> 3) & 1;
    const int r_   = lane >> 2;
    const int c_   = lane & 3;
    const u32 rx8  = (u32)(lane & 7) << 4;

    // ---- warp roles (16 warps) ----
    const int Nw  = w & 7;    // L1/L2: n16 block -> nbase = 16*Nw
    const int Mw  = w >> 3;   // L1/L2: m32 block -> mbase = 32*Mw
    const int Nw3 = w & 3;    // L3: n16 block
    const int Mw3 = w >> 2;   // L3: m16 block (0..3)
    // L4: warps 0..3, m16 block = w

    // ---- x staging role: each thread owns (batch bx, feats fx, fx+1) ----
    const int bx = tid >> 3;
    const int fx = (tid & 7) * 2;
    const u32 xbase = smb + SXS + (u32)(bx * 32 + (((fx >> 3) ^ (bx & 1)) << 4) + (fx & 7) * 2);

    // ---- membranes ----
    float m1[16], m2[16], m3[8], m4[8];
#pragma unroll
    for (int i = 0; i < 16; i++) { m1[i] = 0.f; m2[i] = 0.f; }
#pragma unroll
    for (int i = 0; i < 8; i++) { m3[i] = 0.f; m4[i] = 0.f; }

    __syncthreads();

    // ---- hoist L1 B fragments (constant over t) ----
    u32 bw1[3][4];
#pragma unroll
    for (int lv = 0; lv < 3; lv++)
        ldsm4(bw1[lv], smb + SW1 + (u32)(lv * 4096 + (16 * Nw + brow) * 32)
                       + (((u32)badd << 4) ^ ((u32)(brow & 1) << 4)));

    // ---- stage x(0) ----
    {
        float2 v = *(const float2*)(x + ((size_t)(size_t)Btot * 0 + (size_t)(b0 + bx)) * 16 + fx);
        float e0 = v.x - bfv(v.x), e1 = v.y - bfv(v.y);
        float f0 = e0 - bfv(e0),  f1 = e1 - bfv(e1);
        sts32(xbase,        bfb(v.x) | (bfb(v.y) << 16));
        sts32(xbase + 2048, bfb(e0) | (bfb(e1) << 16));
        sts32(xbase + 4096, bfb(f0) | (bfb(f1) << 16));
    }
    __syncthreads();

    for (int t = 0; t < T_STEPS; t++) {
        // ===== L1: warp M32 x N16, K=16, 6 split terms =====
        {
            float acc[4][4];
#pragma unroll
            for (int j = 0; j < 4; j++)
#pragma unroll
                for (int e = 0; e < 4; e++) acc[j][e] = 0.f;
            const int la[6] = {0, 0, 1, 0, 1, 2};
            const int lb[6] = {0, 1, 0, 2, 1, 0};
#pragma unroll
            for (int M = 0; M < 2; M++) {
                u32 ax[3][4];
#pragma unroll
                for (int lv = 0; lv < 3; lv++)
                    ldsm4(ax[lv], smb + SXS + (u32)(lv * 2048 + (32 * Mw + 16 * M + arow) * 32)
                                  + (((u32)ac << 4) ^ ((u32)(arow & 1) << 4)));
#pragma unroll
                for (int s = 0; s < 6; s++) {
                    mma_bf16(acc[M * 2 + 0], ax[la[s]], bw1[lb[s]][0], bw1[lb[s]][1]);
                    mma_bf16(acc[M * 2 + 1], ax[la[s]], bw1[lb[s]][2], bw1[lb[s]][3]);
                }
            }
#pragma unroll
            for (int M = 0; M < 2; M++)
#pragma unroll
                for (int nb = 0; nb < 2; nb++) {
                    u32 p0, p1;
                    lif4(&m1[(M * 2 + nb) * 4], acc[M * 2 + nb], p0, p1);
                    u32 a0 = smb + SS1 + (u32)((32 * Mw + 16 * M + r_) * 256)
                             + (((u32)(2 * Nw + nb) << 4) ^ ((u32)r_ << 4)) + 4 * c_;
                    sts32(a0, p0);
                    sts32(a0 + 8 * 256, p1);
                }
        }
        __syncthreads();

        // ===== L2: warp M32 x N16, K=128, 3 splits =====
        {
            float acc[4][4];
#pragma unroll
            for (int j = 0; j < 4; j++)
#pragma unroll
                for (int e = 0; e < 4; e++) acc[j][e] = 0.f;
#pragma unroll
            for (int kc = 0; kc < 8; kc++) {
                u32 a_[2][4];
#pragma unroll
                for (int M = 0; M < 2; M++)
                    ldsm4(a_[M], smb + SS1 + (u32)((32 * Mw + 16 * M + arow) * 256)
                                 + (((u32)(2 * kc + ac) << 4) ^ rx8));
#pragma unroll
                for (int s = 0; s < 3; s++) {
                    u32 b_[4];
                    ldsm4(b_, smb + SW2 + (u32)(s * 32768 + (16 * Nw + brow) * 256)
                              + (((u32)(2 * kc + badd) << 4) ^ rx8));
#pragma unroll
                    for (int M = 0; M < 2; M++) {
                        mma_bf16(acc[M * 2 + 0], a_[M], b_[0], b_[1]);
                        mma_bf16(acc[M * 2 + 1], a_[M], b_[2], b_[3]);
                    }
                }
            }
#pragma unroll
            for (int M = 0; M < 2; M++)
#pragma unroll
                for (int nb = 0; nb < 2; nb++) {
                    u32 p0, p1;
                    lif4(&m2[(M * 2 + nb) * 4], acc[M * 2 + nb], p0, p1);
                    u32 a0 = smb + SS2 + (u32)((32 * Mw + 16 * M + r_) * 256)
                             + (((u32)(2 * Nw + nb) << 4) ^ ((u32)r_ << 4)) + 4 * c_;
                    sts32(a0, p0);
                    sts32(a0 + 8 * 256, p1);
                }
        }
        __syncthreads();

        // ---- prefetch x(t+1) into registers (hidden under L3) ----
        float2 xv = make_float2(0.f, 0.f);
        if (t + 1 < T_STEPS)
            xv = *(const float2*)(x + ((size_t)(t + 1) * (size_t)Btot + (size_t)(b0 + bx)) * 16 + fx);

        // ===== L3: warp M16 x N16, K=128, 3 splits =====
        {
            float acc[2][4];
#pragma unroll
            for (int j = 0; j < 2; j++)
#pragma unroll
                for (int e = 0; e < 4; e++) acc[j][e] = 0.f;
#pragma unroll
            for (int kc = 0; kc < 8; kc++) {
                u32 a_[4];
                ldsm4(a_, smb + SS2 + (u32)((16 * Mw3 + arow) * 256)
                          + (((u32)(2 * kc + ac) << 4) ^ rx8));
#pragma unroll
                for (int s = 0; s < 3; s++) {
                    u32 b_[4];
                    ldsm4(b_, smb + SW3 + (u32)(s * 16384 + (16 * Nw3 + brow) * 256)
                              + (((u32)(2 * kc + badd) << 4) ^ rx8));
                    mma_bf16(acc[0], a_, b_[0], b_[1]);
                    mma_bf16(acc[1], a_, b_[2], b_[3]);
                }
            }
#pragma unroll
            for (int nb = 0; nb < 2; nb++) {
                u32 p0, p1;
                lif4(&m3[nb * 4], acc[nb], p0, p1);
                u32 a0 = smb + SS3 + (u32)((16 * Mw3 + r_) * 128)
                         + (((u32)(2 * Nw3 + nb) << 4) ^ ((u32)r_ << 4)) + 4 * c_;
                sts32(a0, p0);
                sts32(a0 + 8 * 128, p1);
            }
        }
        __syncthreads();

        // ===== L4 (warps 0..3): warp M16 x N16 (10 real), K=64 =====
        if (w < 4) {
            float acc[2][4];
#pragma unroll
            for (int j = 0; j < 2; j++)
#pragma unroll
                for (int e = 0; e < 4; e++) acc[j][e] = 0.f;
#pragma unroll
            for (int kc = 0; kc < 4; kc++) {
                u32 a_[4];
                ldsm4(a_, smb + SS3 + (u32)((16 * w + arow) * 128)
                          + (((u32)(2 * kc + ac) << 4) ^ rx8));
#pragma unroll
                for (int s = 0; s < 3; s++) {
                    u32 b_[4];
                    ldsm4(b_, smb + SW4 + (u32)(s * 2048 + brow * 128)
                              + (((u32)(2 * kc + badd) << 4) ^ rx8));
                    mma_bf16(acc[0], a_, b_[0], b_[1]);
                    mma_bf16(acc[1], a_, b_[2], b_[3]);
                }
            }
            u32 q0, q1;
            lif4(&m4[0], acc[0], q0, q1);
            lif4(&m4[4], acc[1], q0, q1);
            float s4[8];
#pragma unroll
            for (int e = 0; e < 8; e++)
                s4[e] = (m4[e] > THR) ? 1.0f : 0.0f;
            size_t row0 = (size_t)t * (size_t)Btot + (size_t)(b0 + 16 * w + r_);
            *(float2*)(out + row0 * 10 + 2 * c_)       = make_float2(s4[0], s4[1]);
            *(float2*)(out + (row0 + 8) * 10 + 2 * c_) = make_float2(s4[2], s4[3]);
            if (c_ == 0) {
                *(float2*)(out + row0 * 10 + 8)       = make_float2(s4[4], s4[5]);
                *(float2*)(out + (row0 + 8) * 10 + 8) = make_float2(s4[6], s4[7]);
            }
        }

        // ---- stage x(t+1) splits (all threads; SXS=SS2 free after L3) ----
        if (t + 1 < T_STEPS) {
            float e0 = xv.x - bfv(xv.x), e1 = xv.y - bfv(xv.y);
            float f0 = e0 - bfv(e0),    f1 = e1 - bfv(e1);
            sts32(xbase,        bfb(xv.x) | (bfb(xv.y) << 16));
            sts32(xbase + 2048, bfb(e0) | (bfb(e1) << 16));
            sts32(xbase + 4096, bfb(f0) | (bfb(f1) << 16));
        }
        __syncthreads();
    }
}

extern "C" void kernel_launch(void* const* d_in, const int* in_sizes, int n_in,
                              void* d_out, int out_size) {
    const float* x  = (const float*)d_in[0];
    const float* w1 = (const float*)d_in[1];
    const float* w2 = (const float*)d_in[2];
    const float* w3 = (const float*)d_in[3];
    const float* w4 = (const float*)d_in[4];
    float* out = (float*)d_out;

    const int Btot = in_sizes[0] / (T_STEPS * 16);  // 65536
    const int grid = Btot / 64;                     // 1024

    cudaFuncSetAttribute(snn_mma_kernel,
                         cudaFuncAttributeMaxDynamicSharedMemorySize,
                         SM_TOTAL);
    snn_mma_kernel<<<grid, THREADS, SM_TOTAL>>>(x, w1, w2, w3, w4, out, Btot);
}

// round 10
// speedup vs baseline: 1.4485x; 1.0537x over previous
#include <cuda_runtime.h>
#include <cuda_bf16.h>

#define THREADS 256
#define T_STEPS 20
#define BETA 0.9f
#define THR 1.0f

typedef unsigned int u32;

// ---- smem byte offsets (all dedicated — phases are folded) ----
#define SW1 0            // 3 x 128 x 32B
#define SW2 12288        // 3 x 128 x 256B
#define SW3 110592       // 3 x 64 x 256B
#define SW4 159744       // 3 x 16 x 128B
#define SS1 165888       // 64 x 256B
#define SS2 182272       // 64 x 256B
#define SS3 198656       // 64 x 128B
#define SXS 206848       // 3 x 64 x 32B
#define SM_TOTAL 212992

__device__ __forceinline__ float bfv(float v) { return __bfloat162float(__float2bfloat16(v)); }
__device__ __forceinline__ u32 bfb(float v) { return (u32)__bfloat16_as_ushort(__float2bfloat16(v)); }

__device__ __forceinline__ void ldsm4(u32 a[4], u32 addr) {
    asm volatile("ldmatrix.sync.aligned.m8n8.x4.shared.b16 {%0,%1,%2,%3}, [%4];"
        : "=r"(a[0]), "=r"(a[1]), "=r"(a[2]), "=r"(a[3]) : "r"(addr));
}
__device__ __forceinline__ void ldsm2(u32 &r0, u32 &r1, u32 addr) {
    asm volatile("ldmatrix.sync.aligned.m8n8.x2.shared.b16 {%0,%1}, [%2];"
        : "=r"(r0), "=r"(r1) : "r"(addr));
}
__device__ __forceinline__ void mma_bf16(float d[4], const u32 a[4], u32 b0, u32 b1) {
    asm volatile("mma.sync.aligned.m16n8k16.row.col.f32.bf16.bf16.f32 "
        "{%0,%1,%2,%3}, {%4,%5,%6,%7}, {%8,%9}, {%0,%1,%2,%3};"
        : "+f"(d[0]), "+f"(d[1]), "+f"(d[2]), "+f"(d[3])
        : "r"(a[0]), "r"(a[1]), "r"(a[2]), "r"(a[3]), "r"(b0), "r"(b1));
}
__device__ __forceinline__ void sts32(u32 addr, u32 v) {
    asm volatile("st.shared.b32 [%0], %1;" :: "r"(addr), "r"(v) : "memory");
}

__device__ __forceinline__ void lif4(float* mem, const float* d, u32 &p0, u32 &p1) {
    float s[4];
#pragma unroll
    for (int e = 0; e < 4; e++) {
        float m = mem[e];
        float reset = (m > THR) ? 1.0f : 0.0f;
        m = fmaf(BETA, m, d[e]) - reset;
        mem[e] = m;
        s[e] = (m > THR) ? 1.0f : 0.0f;
    }
    p0 = (s[0] != 0.0f ? 0x3F80u : 0u) | (s[1] != 0.0f ? 0x3F800000u : 0u);
    p1 = (s[2] != 0.0f ? 0x3F80u : 0u) | (s[3] != 0.0f ? 0x3F800000u : 0u);
}

__global__ void __launch_bounds__(THREADS, 1)
snn_mma_kernel(const float* __restrict__ x,
               const float* __restrict__ w1g,
               const float* __restrict__ w2g,
               const float* __restrict__ w3g,
               const float* __restrict__ w4g,
               float* __restrict__ out,
               int Btot)
{
    extern __shared__ char sm[];
    u32 smb;
    asm("{ .reg .u64 t; cvta.to.shared.u64 t, %1; cvt.u32.u64 %0, t; }"
        : "=r"(smb) : "l"(sm));

    const int tid  = threadIdx.x;
    const int w    = tid >> 5;
    const int lane = tid & 31;
    const int b0   = blockIdx.x * 64;

    // ---- stage weights: 3-way exact bf16 split + XOR swizzle ----
    for (int idx = tid; idx < 128 * 128; idx += THREADS) {
        int n = idx >> 7, k = idx & 127;
        float v = w2g[idx];
        float r1_ = v - bfv(v);
        float r2_ = r1_ - bfv(r1_);
        u32 off = (u32)(n * 256 + (((k >> 3) ^ (n & 7)) << 4) + (k & 7) * 2);
        *(__nv_bfloat16*)(sm + SW2 +     0 + off) = __float2bfloat16(v);
        *(__nv_bfloat16*)(sm + SW2 + 32768 + off) = __float2bfloat16(r1_);
        *(__nv_bfloat16*)(sm + SW2 + 65536 + off) = __float2bfloat16(r2_);
    }
    for (int idx = tid; idx < 64 * 128; idx += THREADS) {
        int n = idx >> 7, k = idx & 127;
        float v = w3g[idx];
        float r1_ = v - bfv(v);
        float r2_ = r1_ - bfv(r1_);
        u32 off = (u32)(n * 256 + (((k >> 3) ^ (n & 7)) << 4) + (k & 7) * 2);
        *(__nv_bfloat16*)(sm + SW3 +     0 + off) = __float2bfloat16(v);
        *(__nv_bfloat16*)(sm + SW3 + 16384 + off) = __float2bfloat16(r1_);
        *(__nv_bfloat16*)(sm + SW3 + 32768 + off) = __float2bfloat16(r2_);
    }
    for (int idx = tid; idx < 128 * 16; idx += THREADS) {
        int n = idx >> 4, k = idx & 15;
        float v = w1g[idx];
        float r1_ = v - bfv(v);
        float r2_ = r1_ - bfv(r1_);
        u32 off = (u32)(n * 32 + (((k >> 3) ^ (n & 1)) << 4) + (k & 7) * 2);
        *(__nv_bfloat16*)(sm + SW1 +    0 + off) = __float2bfloat16(v);
        *(__nv_bfloat16*)(sm + SW1 + 4096 + off) = __float2bfloat16(r1_);
        *(__nv_bfloat16*)(sm + SW1 + 8192 + off) = __float2bfloat16(r2_);
    }
    for (int idx = tid; idx < 16 * 64; idx += THREADS) {
        int n = idx >> 6, k = idx & 63;
        float v = (n < 10) ? w4g[n * 64 + k] : 0.0f;
        float r1_ = v - bfv(v);
        float r2_ = r1_ - bfv(r1_);
        u32 off = (u32)(n * 128 + (((k >> 3) ^ (n & 7)) << 4) + (k & 7) * 2);
        *(__nv_bfloat16*)(sm + SW4 +    0 + off) = __float2bfloat16(v);
        *(__nv_bfloat16*)(sm + SW4 + 2048 + off) = __float2bfloat16(r1_);
        *(__nv_bfloat16*)(sm + SW4 + 4096 + off) = __float2bfloat16(r2_);
    }

    // ---- lane roles ----
    const int arow = ((lane >> 3) & 1) * 8 + (lane & 7);
    const int ac   = lane >> 4;
    const int brow = ((lane >> 4) << 3) + (lane & 7);
    const int badd = (lane >> 3) & 1;
    const int r_   = lane >> 2;
    const int c_   = lane & 3;
    const u32 rx8  = (u32)(lane & 7) << 4;

    // ---- membranes ----
    float m1[32], m2[32], m3[16], m4[4];
#pragma unroll
    for (int i = 0; i < 32; i++) { m1[i] = 0.f; m2[i] = 0.f; }
#pragma unroll
    for (int i = 0; i < 16; i++) m3[i] = 0.f;
#pragma unroll
    for (int i = 0; i < 4; i++)  m4[i] = 0.f;

    const int np3 = w & 3,  bh  = w >> 2;   // L3 role
    const int Mw  = w >> 1, nb4 = w & 1;    // L4 role

    // ---- x staging role ----
    const int bsx = tid >> 2;
    const int f4  = (tid & 3) << 2;
    const u32 xbase = smb + SXS + (u32)(bsx * 32 + (((f4 >> 3) ^ (bsx & 1)) << 4) + (f4 & 7) * 2);

    __syncthreads();

    // ---- hoist L1 B fragments (constant over t) ----
    u32 bw1[3][4];
#pragma unroll
    for (int lv = 0; lv < 3; lv++)
        ldsm4(bw1[lv], smb + SW1 + (u32)(lv * 4096 + (16 * w + brow) * 32)
                       + (((u32)badd << 4) ^ ((u32)(brow & 1) << 4)));

    // ===== helpers (inlined lambdas) =====
    auto stage_x = [&](int t) {
        float4 v = *(const float4*)(x + ((size_t)t * (size_t)Btot + (size_t)(b0 + bsx)) * 16 + f4);
        float e0 = v.x - bfv(v.x), e1 = v.y - bfv(v.y), e2 = v.z - bfv(v.z), e3 = v.w - bfv(v.w);
        float g0 = e0 - bfv(e0), g1 = e1 - bfv(e1), g2 = e2 - bfv(e2), g3 = e3 - bfv(e3);
        sts32(xbase,            bfb(v.x) | (bfb(v.y) << 16));
        sts32(xbase + 4,        bfb(v.z) | (bfb(v.w) << 16));
        sts32(xbase + 2048,     bfb(e0) | (bfb(e1) << 16));
        sts32(xbase + 2048 + 4, bfb(e2) | (bfb(e3) << 16));
        sts32(xbase + 4096,     bfb(g0) | (bfb(g1) << 16));
        sts32(xbase + 4096 + 4, bfb(g2) | (bfb(g3) << 16));
    };

    auto do_L1 = [&]() {
        float acc[32];
#pragma unroll
        for (int i = 0; i < 32; i++) acc[i] = 0.f;
        const int la[6] = {0, 0, 1, 0, 1, 2};
        const int lb[6] = {0, 1, 0, 2, 1, 0};
#pragma unroll
        for (int M = 0; M < 4; M++) {
            u32 ax[3][4];
#pragma unroll
            for (int lv = 0; lv < 3; lv++)
                ldsm4(ax[lv], smb + SXS + (u32)(lv * 2048 + (16 * M + arow) * 32)
                              + (((u32)ac << 4) ^ ((u32)(arow & 1) << 4)));
#pragma unroll
            for (int s = 0; s < 6; s++) {
                mma_bf16(&acc[(M * 2 + 0) * 4], ax[la[s]], bw1[lb[s]][0], bw1[lb[s]][1]);
                mma_bf16(&acc[(M * 2 + 1) * 4], ax[la[s]], bw1[lb[s]][2], bw1[lb[s]][3]);
            }
        }
#pragma unroll
        for (int M = 0; M < 4; M++)
#pragma unroll
            for (int nb = 0; nb < 2; nb++) {
                u32 p0, p1;
                lif4(&m1[(M * 2 + nb) * 4], &acc[(M * 2 + nb) * 4], p0, p1);
                u32 a0 = smb + SS1 + (u32)((16 * M + r_) * 256)
                         + (((u32)(2 * w + nb) << 4) ^ ((u32)r_ << 4)) + 4 * c_;
                sts32(a0, p0);
                sts32(a0 + 8 * 256, p1);
            }
    };

    // ===== prologue: stage x(0), L1(0) =====
    stage_x(0);
    __syncthreads();
    do_L1();
    __syncthreads();

    for (int t = 0; t < T_STEPS; t++) {
        // ===== phase A: L2(t) + prefetch/stage x(t+1) =====
        {
            float4 xv;
            if (t + 1 < T_STEPS)
                xv = *(const float4*)(x + ((size_t)(t + 1) * (size_t)Btot + (size_t)(b0 + bsx)) * 16 + f4);

            float acc[32];
#pragma unroll
            for (int i = 0; i < 32; i++) acc[i] = 0.f;
#pragma unroll
            for (int kc = 0; kc < 8; kc++) {
                u32 a_[4][4];
#pragma unroll
                for (int M = 0; M < 4; M++)
                    ldsm4(a_[M], smb + SS1 + (u32)((16 * M + arow) * 256)
                                 + (((u32)(2 * kc + ac) << 4) ^ rx8));
#pragma unroll
                for (int s = 0; s < 3; s++) {
                    u32 b_[4];
                    ldsm4(b_, smb + SW2 + (u32)(s * 32768 + (16 * w + brow) * 256)
                              + (((u32)(2 * kc + badd) << 4) ^ rx8));
#pragma unroll
                    for (int M = 0; M < 4; M++) {
                        mma_bf16(&acc[(M * 2 + 0) * 4], a_[M], b_[0], b_[1]);
                        mma_bf16(&acc[(M * 2 + 1) * 4], a_[M], b_[2], b_[3]);
                    }
                }
            }
#pragma unroll
            for (int M = 0; M < 4; M++)
#pragma unroll
                for (int nb = 0; nb < 2; nb++) {
                    u32 p0, p1;
                    lif4(&m2[(M * 2 + nb) * 4], &acc[(M * 2 + nb) * 4], p0, p1);
                    u32 a0 = smb + SS2 + (u32)((16 * M + r_) * 256)
                             + (((u32)(2 * w + nb) << 4) ^ ((u32)r_ << 4)) + 4 * c_;
                    sts32(a0, p0);
                    sts32(a0 + 8 * 256, p1);
                }

            if (t + 1 < T_STEPS) {
                float e0 = xv.x - bfv(xv.x), e1 = xv.y - bfv(xv.y), e2 = xv.z - bfv(xv.z), e3 = xv.w - bfv(xv.w);
                float g0 = e0 - bfv(e0), g1 = e1 - bfv(e1), g2 = e2 - bfv(e2), g3 = e3 - bfv(e3);
                sts32(xbase,            bfb(xv.x) | (bfb(xv.y) << 16));
                sts32(xbase + 4,        bfb(xv.z) | (bfb(xv.w) << 16));
                sts32(xbase + 2048,     bfb(e0) | (bfb(e1) << 16));
                sts32(xbase + 2048 + 4, bfb(e2) | (bfb(e3) << 16));
                sts32(xbase + 4096,     bfb(g0) | (bfb(g1) << 16));
                sts32(xbase + 4096 + 4, bfb(g2) | (bfb(g3) << 16));
            }
        }
        __syncthreads();

        // ===== phase B: L3(t) =====
        {
            float acc[16];
#pragma unroll
            for (int i = 0; i < 16; i++) acc[i] = 0.f;
#pragma unroll
            for (int kc = 0; kc < 8; kc++) {
                u32 a_[2][4];
#pragma unroll
                for (int M = 0; M < 2; M++)
                    ldsm4(a_[M], smb + SS2 + (u32)((32 * bh + 16 * M + arow) * 256)
                                 + (((u32)(2 * kc + ac) << 4) ^ rx8));
#pragma unroll
                for (int s = 0; s < 3; s++) {
                    u32 b_[4];
                    ldsm4(b_, smb + SW3 + (u32)(s * 16384 + (16 * np3 + brow) * 256)
                              + (((u32)(2 * kc + badd) << 4) ^ rx8));
#pragma unroll
                    for (int M = 0; M < 2; M++) {
                        mma_bf16(&acc[(M * 2 + 0) * 4], a_[M], b_[0], b_[1]);
                        mma_bf16(&acc[(M * 2 + 1) * 4], a_[M], b_[2], b_[3]);
                    }
                }
            }
#pragma unroll
            for (int M = 0; M < 2; M++)
#pragma unroll
                for (int nb = 0; nb < 2; nb++) {
                    u32 p0, p1;
                    lif4(&m3[(M * 2 + nb) * 4], &acc[(M * 2 + nb) * 4], p0, p1);
                    u32 a0 = smb + SS3 + (u32)((32 * bh + 16 * M + r_) * 128)
                             + (((u32)(2 * np3 + nb) << 4) ^ ((u32)r_ << 4)) + 4 * c_;
                    sts32(a0, p0);
                    sts32(a0 + 8 * 128, p1);
                }
        }
        __syncthreads();

        // ===== phase C: L4(t) + L1(t+1) =====
        {
            float acc[4] = {0.f, 0.f, 0.f, 0.f};
#pragma unroll
            for (int kc = 0; kc < 4; kc++) {
                u32 a_[4];
                ldsm4(a_, smb + SS3 + (u32)((16 * Mw + arow) * 128)
                          + (((u32)(2 * kc + ac) << 4) ^ rx8));
#pragma unroll
                for (int s = 0; s < 3; s++) {
                    u32 b0r, b1r;
                    ldsm2(b0r, b1r, smb + SW4 + (u32)(s * 2048 + (8 * nb4 + (lane & 7)) * 128)
                                  + (((u32)(2 * kc + badd) << 4) ^ ((u32)(lane & 7) << 4)));
                    mma_bf16(acc, a_, b0r, b1r);
                }
            }
            float s4[4];
#pragma unroll
            for (int e = 0; e < 4; e++) {
                float m = m4[e];
                float reset = (m > THR) ? 1.0f : 0.0f;
                m = fmaf(BETA, m, acc[e]) - reset;
                m4[e] = m;
                s4[e] = (m > THR) ? 1.0f : 0.0f;
            }
            size_t row0 = (size_t)t * (size_t)Btot + (size_t)(b0 + 16 * Mw + r_);
            if (nb4 == 0) {
                *(float2*)(out + row0 * 10 + 2 * c_)       = make_float2(s4[0], s4[1]);
                *(float2*)(out + (row0 + 8) * 10 + 2 * c_) = make_float2(s4[2], s4[3]);
            } else if (c_ == 0) {
                *(float2*)(out + row0 * 10 + 8)       = make_float2(s4[0], s4[1]);
                *(float2*)(out + (row0 + 8) * 10 + 8) = make_float2(s4[2], s4[3]);
            }

            if (t + 1 < T_STEPS)
                do_L1();
        }
        __syncthreads();
    }
}

extern "C" void kernel_launch(void* const* d_in, const int* in_sizes, int n_in,
                              void* d_out, int out_size) {
    const float* x  = (const float*)d_in[0];
    const float* w1 = (const float*)d_in[1];
    const float* w2 = (const float*)d_in[2];
    const float* w3 = (const float*)d_in[3];
    const float* w4 = (const float*)d_in[4];
    float* out = (float*)d_out;

    const int Btot = in_sizes[0] / (T_STEPS * 16);  // 65536
    const int grid = Btot / 64;                     // 1024

    cudaFuncSetAttribute(snn_mma_kernel,
                         cudaFuncAttributeMaxDynamicSharedMemorySize,
                         SM_TOTAL);
    snn_mma_kernel<<<grid, THREADS, SM_TOTAL>>>(x, w1, w2, w3, w4, out, Btot);
}